// round 1
// baseline (speedup 1.0000x reference)
#include <cuda_runtime.h>

// ---------------- scratch (no allocations allowed) ----------------
__device__ float g_Gpart[8 * 32 * 64 * 64];   // 4 MB split-K gram partials
__device__ float g_m1part[8 * 32 * 64];       // token-sum partials
__device__ float g_Mt[8 * 64 * 64];           // per-batch mixing matrix, TRANSPOSED [b][j][s]
__device__ float g_alpha[4], g_beta[4], g_gamma[4], g_delta[4], g_wh[4];
__device__ float g_cst[1];

// ---------------- K0: collapse all weights ----------------
// A = wqkv @ w1 (96), B0 = wqkv @ b1 (96), t[c] = w2 . wproj[:,c]
// alpha_h = sum_d Aq*Ak ; beta = Aq*Bk ; gamma = Bq*Ak ; delta = Bq*Bk
// wh[h] = sum_{c in h} t[c]*Av[c] ; cst = sum_c t[c]*Bv_0[c] + w2.bproj + b2
__global__ void setup_kernel(const float* __restrict__ w1, const float* __restrict__ b1,
                             const float* __restrict__ wqkv, const float* __restrict__ wproj,
                             const float* __restrict__ bproj, const float* __restrict__ w2,
                             const float* __restrict__ b2) {
    __shared__ float A[96], B0[96], t[32];
    int tid = threadIdx.x;
    if (tid < 96) {
        float a = 0.f, bb = 0.f;
        #pragma unroll
        for (int c = 0; c < 32; ++c) {
            float wv = wqkv[tid * 32 + c];
            a += wv * w1[c];
            bb += wv * b1[c];
        }
        A[tid] = a; B0[tid] = bb;
    }
    if (tid < 32) {
        float s = 0.f;
        #pragma unroll
        for (int o = 0; o < 32; ++o) s += w2[o] * wproj[o * 32 + tid];
        t[tid] = s;
    }
    __syncthreads();
    if (tid < 4) {
        float al = 0.f, be = 0.f, ga = 0.f, de = 0.f, wh = 0.f;
        #pragma unroll
        for (int dd = 0; dd < 8; ++dd) {
            int c = tid * 8 + dd;
            float aq = A[c], ak = A[32 + c], bq = B0[c], bk = B0[32 + c];
            al += aq * ak; be += aq * bk; ga += bq * ak; de += bq * bk;
            wh += t[c] * A[64 + c];
        }
        g_alpha[tid] = al; g_beta[tid] = be; g_gamma[tid] = ga; g_delta[tid] = de;
        g_wh[tid] = wh;
    }
    if (tid == 4) {
        float c = b2[0];
        #pragma unroll
        for (int o = 0; o < 32; ++o) c += w2[o] * bproj[o];
        #pragma unroll
        for (int cc = 0; cc < 32; ++cc) c += t[cc] * B0[64 + cc];
        g_cst[0] = c;
    }
}

// ---------------- K1: Gram partials ----------------
// grid (8 batches, 32 chunks of 2 image rows within each 64x64 block), 128 threads
// Tt[point(128)][token(64)+pad] ; each warp computes 16 gram rows x 64 cols
__global__ void gram_kernel(const float* __restrict__ x) {
    int b = blockIdx.x, chunk = blockIdx.y;
    int y0 = chunk * 2;
    __shared__ float Tt[128 * 66];
    const float* xb = x + b * 262144;
    int tid = threadIdx.x;

    // load 64 tokens x 128 points (2 rows of each 64x64 block)
    #pragma unroll
    for (int it = 0; it < 16; ++it) {
        int i4 = tid + it * 128;           // 0..2047 float4 index
        int j = i4 >> 5;                   // token
        int rem = i4 & 31;
        int y = rem >> 4, x4 = rem & 15;
        const float4 v = *(const float4*)(xb + ((j >> 3) * 64 + y0 + y) * 512 + (j & 7) * 64 + (x4 << 2));
        int kk = (y << 6) + (x4 << 2);
        float* dst = &Tt[kk * 66 + j];
        dst[0] = v.x; dst[66] = v.y; dst[132] = v.z; dst[198] = v.w;
    }
    __syncthreads();

    int w = tid >> 5, l = tid & 31, ib = w << 4;
    float acc[32];
    #pragma unroll
    for (int i = 0; i < 32; ++i) acc[i] = 0.f;

    for (int kk = 0; kk < 128; ++kk) {
        const float* row = &Tt[kk * 66];
        float bv0 = row[l], bv1 = row[l + 32];
        #pragma unroll
        for (int u = 0; u < 8; ++u) {
            float2 a = *(const float2*)&row[ib + 2 * u];
            acc[4 * u + 0] += a.x * bv0;
            acc[4 * u + 1] += a.x * bv1;
            acc[4 * u + 2] += a.y * bv0;
            acc[4 * u + 3] += a.y * bv1;
        }
    }

    // token sums (partial m1)
    if (tid < 64) {
        float s = 0.f;
        #pragma unroll 8
        for (int kk = 0; kk < 128; ++kk) s += Tt[kk * 66 + tid];
        g_m1part[(b * 32 + chunk) * 64 + tid] = s;
    }

    float* gp = &g_Gpart[((b * 32 + chunk) * 64 + ib) * 64];
    #pragma unroll
    for (int u = 0; u < 8; ++u) {
        gp[(2 * u) * 64 + l]          = acc[4 * u + 0];
        gp[(2 * u) * 64 + l + 32]     = acc[4 * u + 1];
        gp[(2 * u + 1) * 64 + l]      = acc[4 * u + 2];
        gp[(2 * u + 1) * 64 + l + 32] = acc[4 * u + 3];
    }
}

// ---------------- K2: reduce + scores + softmax + mixing matrix ----------------
// grid 8 (batch), 256 threads
__global__ void attn_kernel() {
    int b = blockIdx.x, tid = threadIdx.x;
    __shared__ float Gs[4096];
    __shared__ float Ms[64 * 65];
    __shared__ float m1s[64];

    const float* gp = &g_Gpart[b * 32 * 4096];
    for (int idx = tid; idx < 4096; idx += 256) {
        float s = 0.f;
        #pragma unroll 8
        for (int c = 0; c < 32; ++c) s += gp[c * 4096 + idx];
        Gs[idx] = s;
    }
    for (int idx = tid; idx < 64 * 65; idx += 256) Ms[idx] = 0.f;
    if (tid < 64) {
        const float* mp = &g_m1part[b * 32 * 64];
        float s = 0.f;
        #pragma unroll 8
        for (int c = 0; c < 32; ++c) s += mp[c * 64 + tid];
        m1s[tid] = s;
    }
    __syncthreads();

    int w = tid >> 5, l = tid & 31;
    const float scale = 1.0f / (4096.0f * 2.8284271247461903f);
    for (int h = 0; h < 4; ++h) {
        float al = g_alpha[h] * scale, be = g_beta[h] * scale;
        float ga = g_gamma[h] * scale, de = g_delta[h] * scale * 4096.f;
        float whh = g_wh[h];
        for (int i = w; i < 64; i += 8) {
            float base = be * m1s[i] + de;
            float s0 = al * Gs[i * 64 + l]      + ga * m1s[l]      + base;
            float s1 = al * Gs[i * 64 + l + 32] + ga * m1s[l + 32] + base;
            float mx = fmaxf(s0, s1);
            #pragma unroll
            for (int off = 16; off > 0; off >>= 1)
                mx = fmaxf(mx, __shfl_xor_sync(0xffffffffu, mx, off));
            float e0 = __expf(s0 - mx), e1 = __expf(s1 - mx);
            float sm = e0 + e1;
            #pragma unroll
            for (int off = 16; off > 0; off >>= 1)
                sm += __shfl_xor_sync(0xffffffffu, sm, off);
            float f = whh / sm;
            Ms[i * 65 + l]      += e0 * f;
            Ms[i * 65 + l + 32] += e1 * f;
        }
    }
    __syncthreads();
    // write transposed: g_Mt[b][j][s] = M[s][j]
    for (int idx = tid; idx < 4096; idx += 256) {
        int j = idx >> 6, s = idx & 63;
        g_Mt[b * 4096 + idx] = Ms[s * 65 + j];
    }
}

// ---------------- K3: out = M @ X + const ----------------
// grid (8 batches, 64 y_in rows), 128 threads; each warp computes 16 token rows x 64 cols
__global__ void out_kernel(const float* __restrict__ x, float* __restrict__ out) {
    int b = blockIdx.x, y_in = blockIdx.y;
    int tid = threadIdx.x;
    __shared__ float Mt[4096];      // [j][s]
    __shared__ float V[64 * 66];    // [j][x_in]

    const float* mt = &g_Mt[b * 4096];
    #pragma unroll
    for (int it = 0; it < 8; ++it)
        ((float4*)Mt)[tid + it * 128] = ((const float4*)mt)[tid + it * 128];

    const float* xb = x + b * 262144;
    #pragma unroll
    for (int it = 0; it < 8; ++it) {
        int i4 = tid + it * 128;       // 0..1023
        int j = i4 >> 4, x4 = i4 & 15;
        float4 v = *(const float4*)(xb + ((j >> 3) * 64 + y_in) * 512 + (j & 7) * 64 + (x4 << 2));
        float* dst = &V[j * 66 + (x4 << 2)];
        dst[0] = v.x; dst[1] = v.y; dst[2] = v.z; dst[3] = v.w;
    }
    __syncthreads();

    int w = tid >> 5, l = tid & 31, sb = w << 4;
    float acc[32];
    #pragma unroll
    for (int i = 0; i < 32; ++i) acc[i] = 0.f;

    for (int j = 0; j < 64; ++j) {
        float bv0 = V[j * 66 + l], bv1 = V[j * 66 + l + 32];
        const float* mrow = &Mt[j * 64 + sb];
        #pragma unroll
        for (int u = 0; u < 8; ++u) {
            float2 a = *(const float2*)&mrow[2 * u];
            acc[4 * u + 0] += a.x * bv0;
            acc[4 * u + 1] += a.x * bv1;
            acc[4 * u + 2] += a.y * bv0;
            acc[4 * u + 3] += a.y * bv1;
        }
    }

    float cst = g_cst[0];
    float* ob = out + b * 262144;
    #pragma unroll
    for (int u = 0; u < 8; ++u) {
        int s0 = sb + 2 * u, s1 = s0 + 1;
        int base0 = ((s0 >> 3) * 64 + y_in) * 512 + (s0 & 7) * 64;
        int base1 = ((s1 >> 3) * 64 + y_in) * 512 + (s1 & 7) * 64;
        ob[base0 + l]      = acc[4 * u + 0] + cst;
        ob[base0 + l + 32] = acc[4 * u + 1] + cst;
        ob[base1 + l]      = acc[4 * u + 2] + cst;
        ob[base1 + l + 32] = acc[4 * u + 3] + cst;
    }
}

extern "C" void kernel_launch(void* const* d_in, const int* in_sizes, int n_in,
                              void* d_out, int out_size) {
    const float* x     = (const float*)d_in[0];
    const float* w1    = (const float*)d_in[3];
    const float* b1    = (const float*)d_in[4];
    const float* wqkv  = (const float*)d_in[5];
    const float* wproj = (const float*)d_in[6];
    const float* bproj = (const float*)d_in[7];
    const float* w2    = (const float*)d_in[8];
    const float* b2    = (const float*)d_in[9];
    float* out = (float*)d_out;

    setup_kernel<<<1, 128>>>(w1, b1, wqkv, wproj, bproj, w2, b2);
    gram_kernel<<<dim3(8, 32), 128>>>(x);
    attn_kernel<<<8, 256>>>();
    out_kernel<<<dim3(8, 64), 128>>>(x, out);
}

// round 2
// speedup vs baseline: 1.7770x; 1.7770x over previous
#include <cuda_runtime.h>

// ---------------- scratch ----------------
__device__ float g_Gpart[8 * 32 * 64 * 64];   // split-K gram partials (4 MB)
__device__ float g_m1part[8 * 32 * 64];       // token-sum partials
__device__ float g_M[8 * 64 * 64];            // per-batch mixing matrix, row-major [b][s][j]
__device__ float g_cst[1];

typedef unsigned long long ull;

__device__ __forceinline__ void ffma2(ull& d, ull a, ull b) {
    asm("fma.rn.f32x2 %0, %1, %2, %0;" : "+l"(d) : "l"(a), "l"(b));
}
__device__ __forceinline__ float2 unpack2(ull v) {
    float2 r; asm("mov.b64 {%0, %1}, %2;" : "=f"(r.x), "=f"(r.y) : "l"(v)); return r;
}

// ---------------- K1: Gram partials ----------------
// grid (8 batches, 32 chunks of 2 image rows), 256 threads.
// Token-major smem T2[token][128 pts + pad2]. Dual-k packed FFMA2:
// acc.lo = even-k partial, acc.hi = odd-k partial.
__global__ __launch_bounds__(256) void gram_kernel(const float* __restrict__ x) {
    int b = blockIdx.x, chunk = blockIdx.y;
    int y0 = chunk * 2;
    __shared__ __align__(16) float T2[64 * 130];
    const float* xb = x + b * 262144;
    int tid = threadIdx.x;

    // fill: 64 tokens x 128 points (coalesced float4 global reads)
    #pragma unroll
    for (int it = 0; it < 8; ++it) {
        int i4 = tid + it * 256;            // 0..2047
        int j = i4 >> 5;
        int rem = i4 & 31;
        int y = rem >> 4, x4 = rem & 15;
        float4 v = *(const float4*)(xb + ((j >> 3) * 64 + y0 + y) * 512 + (j & 7) * 64 + (x4 << 2));
        float* dst = &T2[j * 130 + (y << 6) + (x4 << 2)];
        *(float2*)dst = make_float2(v.x, v.y);
        *(float2*)(dst + 2) = make_float2(v.z, v.w);
    }
    __syncthreads();

    int w = tid >> 5, l = tid & 31, rb = w << 3;   // 8 gram rows per warp
    ull acc[16];
    #pragma unroll
    for (int i = 0; i < 16; ++i) acc[i] = 0ull;

    #pragma unroll 2
    for (int kk = 0; kk < 128; kk += 2) {
        ull bv0 = *(const ull*)&T2[l * 130 + kk];          // lane-varying, conflict-free
        ull bv1 = *(const ull*)&T2[(l + 32) * 130 + kk];
        #pragma unroll
        for (int u = 0; u < 8; ++u) {
            ull a = *(const ull*)&T2[(rb + u) * 130 + kk]; // warp-uniform broadcast
            ffma2(acc[2 * u],     a, bv0);
            ffma2(acc[2 * u + 1], a, bv1);
        }
    }

    // token-sum partials
    if (tid < 64) {
        float s = 0.f;
        #pragma unroll 8
        for (int k = 0; k < 128; ++k) s += T2[tid * 130 + k];
        g_m1part[(b * 32 + chunk) * 64 + tid] = s;
    }

    float* gp = &g_Gpart[(b * 32 + chunk) * 4096];
    #pragma unroll
    for (int u = 0; u < 8; ++u) {
        float2 p0 = unpack2(acc[2 * u]);
        float2 p1 = unpack2(acc[2 * u + 1]);
        gp[(rb + u) * 64 + l]      = p0.x + p0.y;
        gp[(rb + u) * 64 + l + 32] = p1.x + p1.y;
    }
}

// ---------------- K2: consts + reduce + softmax + mixing matrix ----------------
// grid (8 batches, 8 row-groups of 8), 256 threads. Each block redundantly
// collapses the tiny weight stack (replaces separate setup kernel).
__global__ __launch_bounds__(256) void attn_kernel(
        const float* __restrict__ w1, const float* __restrict__ b1,
        const float* __restrict__ wqkv, const float* __restrict__ wproj,
        const float* __restrict__ bproj, const float* __restrict__ w2,
        const float* __restrict__ b2) {
    int b = blockIdx.x, i0 = blockIdx.y * 8, tid = threadIdx.x;
    __shared__ float A[96], B0[96], tC[32];
    __shared__ float sal[4], sbe[4], sga[4], sde[4], swh[4], scst[1];
    __shared__ float Gs[512], Ms[512], m1s[64];

    // ---- weight collapse (tiny) ----
    if (tid < 96) {
        float a = 0.f, bb = 0.f;
        #pragma unroll
        for (int c = 0; c < 32; ++c) {
            float wv = wqkv[tid * 32 + c];
            a += wv * w1[c];
            bb += wv * b1[c];
        }
        A[tid] = a; B0[tid] = bb;
    }
    if (tid >= 128 && tid < 160) {
        int c = tid - 128;
        float s = 0.f;
        #pragma unroll
        for (int o = 0; o < 32; ++o) s += w2[o] * wproj[o * 32 + c];
        tC[c] = s;
    }
    __syncthreads();
    if (tid < 4) {
        float al = 0.f, be = 0.f, ga = 0.f, de = 0.f, wh = 0.f;
        #pragma unroll
        for (int dd = 0; dd < 8; ++dd) {
            int c = tid * 8 + dd;
            float aq = A[c], ak = A[32 + c], bq = B0[c], bk = B0[32 + c];
            al += aq * ak; be += aq * bk; ga += bq * ak; de += bq * bk;
            wh += tC[c] * A[64 + c];
        }
        sal[tid] = al; sbe[tid] = be; sga[tid] = ga; sde[tid] = de; swh[tid] = wh;
    }
    if (tid == 4) {
        float c = b2[0];
        #pragma unroll
        for (int o = 0; o < 32; ++o) c += w2[o] * bproj[o];
        #pragma unroll
        for (int cc = 0; cc < 32; ++cc) c += tC[cc] * B0[64 + cc];
        scst[0] = c;
        g_cst[0] = c;   // identical value from every block (deterministic)
    }

    // ---- reduce this block's 8 Gram rows + m1 ----
    const float* gp = &g_Gpart[b * 32 * 4096 + i0 * 64];
    #pragma unroll
    for (int rep = 0; rep < 2; ++rep) {
        int e = tid + rep * 256;
        float s = 0.f;
        #pragma unroll 8
        for (int c = 0; c < 32; ++c) s += gp[c * 4096 + e];
        Gs[e] = s;
        Ms[e] = 0.f;
    }
    if (tid < 64) {
        const float* mp = &g_m1part[b * 32 * 64];
        float s = 0.f;
        #pragma unroll 8
        for (int c = 0; c < 32; ++c) s += mp[c * 64 + tid];
        m1s[tid] = s;
    }
    __syncthreads();

    // ---- softmax: warp w owns row i0+w ----
    int w = tid >> 5, l = tid & 31;
    const float scale = 1.0f / (4096.0f * 2.8284271247461903f);
    float g0 = Gs[w * 64 + l], g1 = Gs[w * 64 + l + 32];
    float m1i = m1s[i0 + w], m1l = m1s[l], m1l2 = m1s[l + 32];
    float acc0 = 0.f, acc1 = 0.f;
    #pragma unroll
    for (int h = 0; h < 4; ++h) {
        float al = sal[h] * scale, be = sbe[h] * scale;
        float ga = sga[h] * scale, de = sde[h] * scale * 4096.f;
        float whh = swh[h];
        float base = be * m1i + de;
        float s0 = al * g0 + ga * m1l  + base;
        float s1 = al * g1 + ga * m1l2 + base;
        float mx = fmaxf(s0, s1);
        #pragma unroll
        for (int off = 16; off > 0; off >>= 1)
            mx = fmaxf(mx, __shfl_xor_sync(0xffffffffu, mx, off));
        float e0 = __expf(s0 - mx), e1 = __expf(s1 - mx);
        float sm = e0 + e1;
        #pragma unroll
        for (int off = 16; off > 0; off >>= 1)
            sm += __shfl_xor_sync(0xffffffffu, sm, off);
        float f = whh / sm;
        acc0 += e0 * f; acc1 += e1 * f;
    }
    Ms[w * 64 + l] = acc0;
    Ms[w * 64 + l + 32] = acc1;
    __syncthreads();

    float* mo = &g_M[b * 4096 + i0 * 64];
    mo[tid] = Ms[tid];
    mo[tid + 256] = Ms[tid + 256];
}

// ---------------- K3: out = M @ X + const ----------------
// grid (8 batches, 32 y-pairs), 256 threads. M row-major in smem (broadcast
// LDS.64 over contiguous j-pairs), V transposed [x][j] for packed j-pairs.
__global__ __launch_bounds__(256) void out_kernel(const float* __restrict__ x,
                                                  float* __restrict__ out) {
    int b = blockIdx.x, y0 = blockIdx.y * 2;
    int tid = threadIdx.x;
    __shared__ __align__(16) float Msm[4096];     // [s][j]
    __shared__ __align__(16) float Vt[64 * 66];   // [x][j]

    const float* mg = &g_M[b * 4096];
    #pragma unroll
    for (int it = 0; it < 4; ++it)
        ((float4*)Msm)[tid + it * 256] = ((const float4*)mg)[tid + it * 256];

    const float* xb = x + b * 262144;
    float* ob = out + b * 262144;
    float cst = g_cst[0];
    int w = tid >> 5, l = tid & 31, rb = w << 3;

    for (int yy = 0; yy < 2; ++yy) {
        int y = y0 + yy;
        __syncthreads();
        // fill Vt[x][j] (transpose in smem)
        #pragma unroll
        for (int it = 0; it < 4; ++it) {
            int i4 = tid + it * 256;         // 0..1023
            int j = i4 >> 4, x4 = i4 & 15;
            float4 v = *(const float4*)(xb + ((j >> 3) * 64 + y) * 512 + (j & 7) * 64 + (x4 << 2));
            Vt[((x4 << 2) + 0) * 66 + j] = v.x;
            Vt[((x4 << 2) + 1) * 66 + j] = v.y;
            Vt[((x4 << 2) + 2) * 66 + j] = v.z;
            Vt[((x4 << 2) + 3) * 66 + j] = v.w;
        }
        __syncthreads();

        ull acc[16];
        #pragma unroll
        for (int i = 0; i < 16; ++i) acc[i] = 0ull;

        #pragma unroll 2
        for (int jp = 0; jp < 64; jp += 2) {
            ull v0 = *(const ull*)&Vt[l * 66 + jp];          // lane-varying, conflict-free
            ull v1 = *(const ull*)&Vt[(l + 32) * 66 + jp];
            #pragma unroll
            for (int u = 0; u < 8; ++u) {
                ull m = *(const ull*)&Msm[(rb + u) * 64 + jp]; // broadcast
                ffma2(acc[2 * u],     m, v0);
                ffma2(acc[2 * u + 1], m, v1);
            }
        }

        #pragma unroll
        for (int u = 0; u < 8; ++u) {
            int s = rb + u;
            float2 p0 = unpack2(acc[2 * u]);
            float2 p1 = unpack2(acc[2 * u + 1]);
            int base = ((s >> 3) * 64 + y) * 512 + (s & 7) * 64;
            ob[base + l]      = p0.x + p0.y + cst;
            ob[base + l + 32] = p1.x + p1.y + cst;
        }
    }
}

extern "C" void kernel_launch(void* const* d_in, const int* in_sizes, int n_in,
                              void* d_out, int out_size) {
    const float* x     = (const float*)d_in[0];
    const float* w1    = (const float*)d_in[3];
    const float* b1    = (const float*)d_in[4];
    const float* wqkv  = (const float*)d_in[5];
    const float* wproj = (const float*)d_in[6];
    const float* bproj = (const float*)d_in[7];
    const float* w2    = (const float*)d_in[8];
    const float* b2    = (const float*)d_in[9];
    float* out = (float*)d_out;

    gram_kernel<<<dim3(8, 32), 256>>>(x);
    attn_kernel<<<dim3(8, 8), 256>>>(w1, b1, wqkv, wproj, bproj, w2, b2);
    out_kernel<<<dim3(8, 32), 256>>>(x, out);
}